// round 6
// baseline (speedup 1.0000x reference)
#include <cuda_runtime.h>
#include <cuda_bf16.h>

// BundleAdjustment, round 6:
//  - NO 64MB scratch: gather raw patch float2 + elev float (L2-resident), trig in-kernel
//  - full pose table exact in 224KB smem (quat float4 + planar tx/ty/tz)
//  - 4 edges/thread, all gathers issued before consumption (MLP)
//  - elev residual folded into main kernel (streams on idle DRAM pipe)

#define R_MIN   0.5f
#define R_MAX   30.0f
#define BINS    512.0f
#define BEAMS   512.0f
#define FOV_H   2.0943951f

#define E_NUM   4194304
#define P_NUM   8192

// Scratch (device globals -- allocation-free per harness rules)
__device__ float4 g_quat[P_NUM];          // 128 KB: (qx, qy, qz, qw) exact
__device__ float  g_tx[P_NUM];            // 32 KB each
__device__ float  g_ty[P_NUM];
__device__ float  g_tz[P_NUM];

// ---------------- Tiny pose prepass ----------------
__global__ __launch_bounds__(256) void pose_prepass(
    const float* __restrict__ poses,
    const float* __restrict__ init_poses,
    float*       __restrict__ out_pose,      // out + 2E
    int P7)
{
    const int tid = blockIdx.x * blockDim.x + threadIdx.x;
    const int nv  = P7 >> 2;   // 57344 / 4 = 14336, vectorized residual
    if (tid < nv) {
        const float4 a = __ldg(((const float4*)poses) + tid);
        const float4 b = __ldg(((const float4*)init_poses) + tid);
        ((float4*)out_pose)[tid] = make_float4(a.x - b.x, a.y - b.y, a.z - b.z, a.w - b.w);
    }
    if (tid < P_NUM) {
        const float* p = poses + 7 * tid;
        g_tx[tid]   = p[0];
        g_ty[tid]   = p[1];
        g_tz[tid]   = p[2];
        g_quat[tid] = make_float4(p[3], p[4], p[5], p[6]);
    }
}

// ---------------- Main ----------------
struct SmemTables {
    const float4* q;
    const float*  tx;
    const float*  ty;
    const float*  tz;
};

// Compute one edge given pre-gathered patch polar data.
__device__ __forceinline__ float2 project_one(const SmemTables& S,
                                              float2 pc, float ph,
                                              int s, int t, float2 tg)
{
    // polar -> local cartesian
    float st, ct, sph, cph;
    __sincosf(pc.y, &st, &ct);
    __sincosf(ph,   &sph, &cph);
    const float rcp = pc.x * cph;
    float vx = rcp * ct;
    float vy = rcp * st;
    float vz = pc.x * sph;

    // src pose: rotate + translate
    {
        const float4 q = S.q[s];
        const float qx = q.x, qy = q.y, qz = q.z, qw = q.w;
        const float tx = 2.0f * (qy * vz - qz * vy);
        const float ty = 2.0f * (qz * vx - qx * vz);
        const float tz = 2.0f * (qx * vy - qy * vx);
        const float rx = vx + qw * tx + (qy * tz - qz * ty);
        const float ry = vy + qw * ty + (qz * tx - qx * tz);
        const float rz = vz + qw * tz + (qx * ty - qy * tx);
        vx = rx + S.tx[s]; vy = ry + S.ty[s]; vz = rz + S.tz[s];
    }

    // tgt pose: translate + inverse rotate
    vx -= S.tx[t]; vy -= S.ty[t]; vz -= S.tz[t];
    float lx, ly, lz;
    {
        const float4 q = S.q[t];
        const float qx = -q.x, qy = -q.y, qz = -q.z, qw = q.w;
        const float tx = 2.0f * (qy * vz - qz * vy);
        const float ty = 2.0f * (qz * vx - qx * vz);
        const float tz = 2.0f * (qx * vy - qy * vx);
        lx = vx + qw * tx + (qy * tz - qz * ty);
        ly = vy + qw * ty + (qz * tx - qx * tz);
        lz = vz + qw * tz + (qx * ty - qy * tx);
    }

    const float r3 = sqrtf(lx * lx + ly * ly + lz * lz);
    const float th = atan2f(ly, lx);

    float2 res;
    res.x = (r3 - tg.x) * (BINS  / (R_MAX - R_MIN));
    res.y = (th - tg.y) * (BEAMS / FOV_H);
    return res;
}

__global__ __launch_bounds__(1024) void ba_main(
    const float* __restrict__ patch_coords,  // float2 per patch
    const float* __restrict__ elev,
    const float* __restrict__ init_elev,
    const float* __restrict__ target,        // float2 per edge
    const int*   __restrict__ src_idx,
    const int*   __restrict__ tgt_idx,
    const int*   __restrict__ patch_idx,
    float*       __restrict__ out,           // residual_proj base
    float*       __restrict__ out_elev,      // out + 2E + P7
    int E)
{
    extern __shared__ char smem[];
    float4* s_q  = (float4*)smem;                          // 128 KB
    float*  s_tx = (float*)(smem + P_NUM * 16);            //  32 KB
    float*  s_ty = (float*)(smem + P_NUM * 20);            //  32 KB
    float*  s_tz = (float*)(smem + P_NUM * 24);            //  32 KB

    for (int i = threadIdx.x; i < P_NUM; i += blockDim.x) {
        s_q[i]  = g_quat[i];
        s_tx[i] = g_tx[i];
        s_ty[i] = g_ty[i];
        s_tz[i] = g_tz[i];
    }
    __syncthreads();

    SmemTables S{s_q, s_tx, s_ty, s_tz};

    const float2* patch2 = (const float2*)patch_coords;
    const int quads  = E >> 2;               // E divisible by 4
    const int stride = gridDim.x * blockDim.x;

    for (int tid = blockIdx.x * blockDim.x + threadIdx.x; tid < quads; tid += stride) {
        // ---- streamed elev residual (coalesced, rides DRAM) ----
        {
            const float4 e4 = __ldg(((const float4*)elev) + tid);
            const float4 i4 = __ldg(((const float4*)init_elev) + tid);
            ((float4*)out_elev)[tid] =
                make_float4(e4.x - i4.x, e4.y - i4.y, e4.z - i4.z, e4.w - i4.w);
        }

        // ---- 4 edges: load everything up front for MLP ----
        const int4   s4   = __ldg(((const int4*)src_idx)   + tid);
        const int4   t4   = __ldg(((const int4*)tgt_idx)   + tid);
        const int4   p4   = __ldg(((const int4*)patch_idx) + tid);
        const float4 tg01 = __ldg(((const float4*)target)  + 2 * tid);
        const float4 tg23 = __ldg(((const float4*)target)  + 2 * tid + 1);

        const float2 pc0 = __ldg(patch2 + p4.x);
        const float2 pc1 = __ldg(patch2 + p4.y);
        const float2 pc2 = __ldg(patch2 + p4.z);
        const float2 pc3 = __ldg(patch2 + p4.w);
        const float  ph0 = __ldg(elev + p4.x);
        const float  ph1 = __ldg(elev + p4.y);
        const float  ph2 = __ldg(elev + p4.z);
        const float  ph3 = __ldg(elev + p4.w);

        const float2 r0 = project_one(S, pc0, ph0, s4.x, t4.x, make_float2(tg01.x, tg01.y));
        const float2 r1 = project_one(S, pc1, ph1, s4.y, t4.y, make_float2(tg01.z, tg01.w));
        const float2 r2 = project_one(S, pc2, ph2, s4.z, t4.z, make_float2(tg23.x, tg23.y));
        const float2 r3 = project_one(S, pc3, ph3, s4.w, t4.w, make_float2(tg23.z, tg23.w));

        ((float4*)out)[2 * tid]     = make_float4(r0.x, r0.y, r1.x, r1.y);
        ((float4*)out)[2 * tid + 1] = make_float4(r2.x, r2.y, r3.x, r3.y);
    }
}

extern "C" void kernel_launch(void* const* d_in, const int* in_sizes, int n_in,
                              void* d_out, int out_size)
{
    const float* poses        = (const float*)d_in[0];
    const float* init_poses   = (const float*)d_in[1];
    const float* patch_coords = (const float*)d_in[2];
    const float* elev         = (const float*)d_in[3];
    const float* init_elev    = (const float*)d_in[4];
    const float* target       = (const float*)d_in[5];
    const int*   src_idx      = (const int*)d_in[6];
    const int*   tgt_idx      = (const int*)d_in[7];
    const int*   patch_idx    = (const int*)d_in[8];
    float*       out          = (float*)d_out;

    const int E  = in_sizes[8];   // 4194304
    const int P7 = in_sizes[0];   // 57344
    const long long proj_elems = 2LL * E;

    // tiny pose prepass
    {
        const int threads = 256;
        const int work = P7 >> 2;  // 14336 (covers P_NUM=8192 too)
        const int blocks = (work + threads - 1) / threads;
        pose_prepass<<<blocks, threads>>>(poses, init_poses, out + proj_elems, P7);
    }

    // main: 224KB smem pose table, 1 block/SM, 4 edges/thread
    {
        const int threads = 1024;
        const int smem_bytes = P_NUM * 28;  // 229376
        cudaFuncSetAttribute(ba_main, cudaFuncAttributeMaxDynamicSharedMemorySize, smem_bytes);
        const int blocks = 148;
        ba_main<<<blocks, threads, smem_bytes>>>(
            patch_coords, elev, init_elev, target,
            src_idx, tgt_idx, patch_idx,
            out, out + proj_elems + P7, E);
    }
}

// round 7
// speedup vs baseline: 2.4091x; 2.4091x over previous
#include <cuda_runtime.h>
#include <cuda_bf16.h>

// BundleAdjustment, round 7: R3 structure (high occupancy, no smem) minus the
// 64MB scratch.
//  - tiny pose prepass: pose residual + pack pose into 2x float4 (256 KB, L2/L1-resident)
//  - main: 2 edges/thread, raw patch float2 + elev float gathers (L2-resident),
//    trig in-kernel, elev residual folded in as a coalesced stream.

#define R_MIN   0.5f
#define R_MAX   30.0f
#define BINS    512.0f
#define BEAMS   512.0f
#define FOV_H   2.0943951f

#define P_NUM   8192

// Scratch (device globals -- allocation-free per harness rules)
__device__ float4 g_pose_A[P_NUM];   // 128 KB: (tx, ty, tz, qx)
__device__ float4 g_pose_B[P_NUM];   // 128 KB: (qy, qz, qw, 0)

// ---------------- Tiny pose prepass ----------------
__global__ __launch_bounds__(256) void pose_prepass(
    const float* __restrict__ poses,
    const float* __restrict__ init_poses,
    float*       __restrict__ out_pose,      // out + 2E
    int P7)
{
    const int tid = blockIdx.x * blockDim.x + threadIdx.x;
    const int nv  = P7 >> 2;                 // 14336 float4 residuals
    if (tid < nv) {
        const float4 a = __ldg(((const float4*)poses) + tid);
        const float4 b = __ldg(((const float4*)init_poses) + tid);
        ((float4*)out_pose)[tid] = make_float4(a.x - b.x, a.y - b.y, a.z - b.z, a.w - b.w);
    }
    if (tid < P_NUM) {
        const float* p = poses + 7 * tid;
        g_pose_A[tid] = make_float4(p[0], p[1], p[2], p[3]);
        g_pose_B[tid] = make_float4(p[4], p[5], p[6], 0.0f);
    }
}

// ---------------- Main ----------------
__device__ __forceinline__ float2 project_one(float2 pc, float ph,
                                              int s, int t, float2 tg)
{
    // polar -> local cartesian
    float st, ct, sph, cph;
    __sincosf(pc.y, &st, &ct);
    __sincosf(ph,   &sph, &cph);
    const float rcp = pc.x * cph;
    float vx = rcp * ct;
    float vy = rcp * st;
    float vz = pc.x * sph;

    // src pose: rotate + translate
    const float4 sa = __ldg(&g_pose_A[s]);
    const float4 sb = __ldg(&g_pose_B[s]);
    {
        const float qx = sa.w, qy = sb.x, qz = sb.y, qw = sb.z;
        const float tx = 2.0f * (qy * vz - qz * vy);
        const float ty = 2.0f * (qz * vx - qx * vz);
        const float tz = 2.0f * (qx * vy - qy * vx);
        const float rx = vx + qw * tx + (qy * tz - qz * ty);
        const float ry = vy + qw * ty + (qz * tx - qx * tz);
        const float rz = vz + qw * tz + (qx * ty - qy * tx);
        vx = rx + sa.x; vy = ry + sa.y; vz = rz + sa.z;
    }

    // tgt pose: translate + inverse rotate
    const float4 ta = __ldg(&g_pose_A[t]);
    const float4 tb = __ldg(&g_pose_B[t]);
    vx -= ta.x; vy -= ta.y; vz -= ta.z;
    float lx, ly, lz;
    {
        const float qx = -ta.w, qy = -tb.x, qz = -tb.y, qw = tb.z;
        const float tx = 2.0f * (qy * vz - qz * vy);
        const float ty = 2.0f * (qz * vx - qx * vz);
        const float tz = 2.0f * (qx * vy - qy * vx);
        lx = vx + qw * tx + (qy * tz - qz * ty);
        ly = vy + qw * ty + (qz * tx - qx * tz);
        lz = vz + qw * tz + (qx * ty - qy * tx);
    }

    const float r3 = sqrtf(lx * lx + ly * ly + lz * lz);
    const float th = atan2f(ly, lx);

    float2 res;
    res.x = (r3 - tg.x) * (BINS  / (R_MAX - R_MIN));
    res.y = (th - tg.y) * (BEAMS / FOV_H);
    return res;
}

__global__ __launch_bounds__(256) void ba_main(
    const float* __restrict__ patch_coords,  // float2 per patch
    const float* __restrict__ elev,
    const float* __restrict__ init_elev,
    const float* __restrict__ target,        // float2 per edge
    const int*   __restrict__ src_idx,
    const int*   __restrict__ tgt_idx,
    const int*   __restrict__ patch_idx,
    float*       __restrict__ out,           // residual_proj base
    float*       __restrict__ out_elev,      // out + 2E + P7
    int E)
{
    const int tid   = blockIdx.x * blockDim.x + threadIdx.x;
    const int pairs = E >> 1;
    if (tid >= pairs) return;

    // ---- coalesced elev residual (2 elems) ----
    {
        const float2 e2 = __ldg(((const float2*)elev) + tid);
        const float2 i2 = __ldg(((const float2*)init_elev) + tid);
        ((float2*)out_elev)[tid] = make_float2(e2.x - i2.x, e2.y - i2.y);
    }

    // ---- 2 edges: batch all loads for MLP ----
    const int2   sp = __ldg(((const int2*)src_idx)   + tid);
    const int2   tp = __ldg(((const int2*)tgt_idx)   + tid);
    const int2   pp = __ldg(((const int2*)patch_idx) + tid);
    const float4 tg = __ldg(((const float4*)target)  + tid);

    const float2* patch2 = (const float2*)patch_coords;
    const float2 pc0 = __ldg(patch2 + pp.x);
    const float2 pc1 = __ldg(patch2 + pp.y);
    const float  ph0 = __ldg(elev + pp.x);
    const float  ph1 = __ldg(elev + pp.y);

    const float2 r0 = project_one(pc0, ph0, sp.x, tp.x, make_float2(tg.x, tg.y));
    const float2 r1 = project_one(pc1, ph1, sp.y, tp.y, make_float2(tg.z, tg.w));

    ((float4*)out)[tid] = make_float4(r0.x, r0.y, r1.x, r1.y);
}

extern "C" void kernel_launch(void* const* d_in, const int* in_sizes, int n_in,
                              void* d_out, int out_size)
{
    const float* poses        = (const float*)d_in[0];
    const float* init_poses   = (const float*)d_in[1];
    const float* patch_coords = (const float*)d_in[2];
    const float* elev         = (const float*)d_in[3];
    const float* init_elev    = (const float*)d_in[4];
    const float* target       = (const float*)d_in[5];
    const int*   src_idx      = (const int*)d_in[6];
    const int*   tgt_idx      = (const int*)d_in[7];
    const int*   patch_idx    = (const int*)d_in[8];
    float*       out          = (float*)d_out;

    const int E  = in_sizes[8];   // 4194304
    const int P7 = in_sizes[0];   // 57344
    const long long proj_elems = 2LL * E;

    // tiny pose prepass
    {
        const int threads = 256;
        const int work = P7 >> 2;  // 14336 threads (covers P_NUM=8192)
        const int blocks = (work + threads - 1) / threads;
        pose_prepass<<<blocks, threads>>>(poses, init_poses, out + proj_elems, P7);
    }

    // main: 2 edges/thread, high occupancy, no smem
    {
        const int threads = 256;
        const int pairs = E >> 1;
        const int blocks = (pairs + threads - 1) / threads;
        ba_main<<<blocks, threads>>>(
            patch_coords, elev, init_elev, target,
            src_idx, tgt_idx, patch_idx,
            out, out + proj_elems + P7, E);
    }
}

// round 9
// speedup vs baseline: 2.4673x; 1.0242x over previous
#include <cuda_runtime.h>
#include <cuda_bf16.h>

// BundleAdjustment, round 9: R7 structure + cache-policy separation.
//  - pose tables (high reuse, 256KB): __ldg -> L1-resident
//  - patch gathers + streams (zero L1 reuse): __ldcg -> L2 only, stop evicting poses
//  - exact float32 arithmetic everywhere (lossy paths are dead: R4, R8)

#define R_MIN   0.5f
#define R_MAX   30.0f
#define BINS    512.0f
#define BEAMS   512.0f
#define FOV_H   2.0943951f

#define P_NUM   8192

// Scratch (device globals -- allocation-free per harness rules)
__device__ float4 g_pose_A[P_NUM];   // 128 KB: (tx, ty, tz, qx)
__device__ float4 g_pose_B[P_NUM];   // 128 KB: (qy, qz, qw, 0)

// ---------------- Tiny pose prepass ----------------
__global__ __launch_bounds__(256) void pose_prepass(
    const float* __restrict__ poses,
    const float* __restrict__ init_poses,
    float*       __restrict__ out_pose,      // out + 2E
    int P7)
{
    const int tid = blockIdx.x * blockDim.x + threadIdx.x;
    const int nv  = P7 >> 2;                 // 14336 float4 residuals
    if (tid < nv) {
        const float4 a = __ldcg(((const float4*)poses) + tid);
        const float4 b = __ldcg(((const float4*)init_poses) + tid);
        ((float4*)out_pose)[tid] = make_float4(a.x - b.x, a.y - b.y, a.z - b.z, a.w - b.w);
    }
    if (tid < P_NUM) {
        const float* p = poses + 7 * tid;
        g_pose_A[tid] = make_float4(p[0], p[1], p[2], p[3]);
        g_pose_B[tid] = make_float4(p[4], p[5], p[6], 0.0f);
    }
}

// ---------------- Main ----------------
__device__ __forceinline__ float2 project_one(float2 pc, float ph,
                                              int s, int t, float2 tg)
{
    // polar -> local cartesian
    float st, ct, sph, cph;
    __sincosf(pc.y, &st, &ct);
    __sincosf(ph,   &sph, &cph);
    const float rcp = pc.x * cph;
    float vx = rcp * ct;
    float vy = rcp * st;
    float vz = pc.x * sph;

    // src pose: rotate + translate (L1-resident tables)
    const float4 sa = __ldg(&g_pose_A[s]);
    const float4 sb = __ldg(&g_pose_B[s]);
    {
        const float qx = sa.w, qy = sb.x, qz = sb.y, qw = sb.z;
        const float tx = 2.0f * (qy * vz - qz * vy);
        const float ty = 2.0f * (qz * vx - qx * vz);
        const float tz = 2.0f * (qx * vy - qy * vx);
        const float rx = vx + qw * tx + (qy * tz - qz * ty);
        const float ry = vy + qw * ty + (qz * tx - qx * tz);
        const float rz = vz + qw * tz + (qx * ty - qy * tx);
        vx = rx + sa.x; vy = ry + sa.y; vz = rz + sa.z;
    }

    // tgt pose: translate + inverse rotate
    const float4 ta = __ldg(&g_pose_A[t]);
    const float4 tb = __ldg(&g_pose_B[t]);
    vx -= ta.x; vy -= ta.y; vz -= ta.z;
    float lx, ly, lz;
    {
        const float qx = -ta.w, qy = -tb.x, qz = -tb.y, qw = tb.z;
        const float tx = 2.0f * (qy * vz - qz * vy);
        const float ty = 2.0f * (qz * vx - qx * vz);
        const float tz = 2.0f * (qx * vy - qy * vx);
        lx = vx + qw * tx + (qy * tz - qz * ty);
        ly = vy + qw * ty + (qz * tx - qx * tz);
        lz = vz + qw * tz + (qx * ty - qy * tx);
    }

    const float r3 = sqrtf(lx * lx + ly * ly + lz * lz);
    const float th = atan2f(ly, lx);

    float2 res;
    res.x = (r3 - tg.x) * (BINS  / (R_MAX - R_MIN));
    res.y = (th - tg.y) * (BEAMS / FOV_H);
    return res;
}

__global__ __launch_bounds__(256) void ba_main(
    const float* __restrict__ patch_coords,  // float2 per patch
    const float* __restrict__ elev,
    const float* __restrict__ init_elev,
    const float* __restrict__ target,        // float2 per edge
    const int*   __restrict__ src_idx,
    const int*   __restrict__ tgt_idx,
    const int*   __restrict__ patch_idx,
    float*       __restrict__ out,           // residual_proj base
    float*       __restrict__ out_elev,      // out + 2E + P7
    int E)
{
    const int tid   = blockIdx.x * blockDim.x + threadIdx.x;
    const int pairs = E >> 1;
    if (tid >= pairs) return;

    // ---- coalesced elev residual (zero reuse -> L2 only) ----
    {
        const float2 e2 = __ldcg(((const float2*)elev) + tid);
        const float2 i2 = __ldcg(((const float2*)init_elev) + tid);
        ((float2*)out_elev)[tid] = make_float2(e2.x - i2.x, e2.y - i2.y);
    }

    // ---- 2 edges: batch all loads for MLP; streams + patch gathers bypass L1 ----
    const int2   sp = __ldcg(((const int2*)src_idx)   + tid);
    const int2   tp = __ldcg(((const int2*)tgt_idx)   + tid);
    const int2   pp = __ldcg(((const int2*)patch_idx) + tid);
    const float4 tg = __ldcg(((const float4*)target)  + tid);

    const float2* patch2 = (const float2*)patch_coords;
    const float2 pc0 = __ldcg(patch2 + pp.x);
    const float2 pc1 = __ldcg(patch2 + pp.y);
    const float  ph0 = __ldcg(elev + pp.x);
    const float  ph1 = __ldcg(elev + pp.y);

    const float2 r0 = project_one(pc0, ph0, sp.x, tp.x, make_float2(tg.x, tg.y));
    const float2 r1 = project_one(pc1, ph1, sp.y, tp.y, make_float2(tg.z, tg.w));

    ((float4*)out)[tid] = make_float4(r0.x, r0.y, r1.x, r1.y);
}

extern "C" void kernel_launch(void* const* d_in, const int* in_sizes, int n_in,
                              void* d_out, int out_size)
{
    const float* poses        = (const float*)d_in[0];
    const float* init_poses   = (const float*)d_in[1];
    const float* patch_coords = (const float*)d_in[2];
    const float* elev         = (const float*)d_in[3];
    const float* init_elev    = (const float*)d_in[4];
    const float* target       = (const float*)d_in[5];
    const int*   src_idx      = (const int*)d_in[6];
    const int*   tgt_idx      = (const int*)d_in[7];
    const int*   patch_idx    = (const int*)d_in[8];
    float*       out          = (float*)d_out;

    const int E  = in_sizes[8];   // 4194304
    const int P7 = in_sizes[0];   // 57344
    const long long proj_elems = 2LL * E;

    // tiny pose prepass
    {
        const int threads = 256;
        const int work = P7 >> 2;  // 14336 threads (covers P_NUM=8192)
        const int blocks = (work + threads - 1) / threads;
        pose_prepass<<<blocks, threads>>>(poses, init_poses, out + proj_elems, P7);
    }

    // main: 2 edges/thread, high occupancy, cache-policy split
    {
        const int threads = 256;
        const int pairs = E >> 1;
        const int blocks = (pairs + threads - 1) / threads;
        ba_main<<<blocks, threads>>>(
            patch_coords, elev, init_elev, target,
            src_idx, tgt_idx, patch_idx,
            out, out + proj_elems + P7, E);
    }
}